// round 1
// baseline (speedup 1.0000x reference)
#include <cuda_runtime.h>
#include <stdint.h>

#define IMGD   192
#define PATCHD 96
#define PVOX   (PATCHD*PATCHD*PATCHD)         // 884736
#define VVOX   (IMGD*IMGD*IMGD)               // 7077888
#define K_PRE  1000
#define MAX_OUT 100
#define NBINS  65536
#define CAND_CAP 4096
#define SCORE_THR 0.01f
#define MIN_SIZE  0.01f
#define IOU_THR   0.1f
#define CLS_OFF   384.0f   // 2.0 * 192.0

// ---------------- device scratch (no allocations allowed) ----------------
__device__ unsigned int      g_hist[NBINS];
__device__ unsigned int      g_cand_count;
__device__ int               g_thresh_bin;
__device__ unsigned long long g_cands[CAND_CAP];
__device__ float             g_box [K_PRE*6];
__device__ float             g_obox[K_PRE*6];
__device__ float             g_sc  [K_PRE];
__device__ int               g_lab [K_PRE];
__device__ unsigned char     g_validb[K_PRE];
__device__ unsigned int      g_sup [K_PRE*32];

__device__ __forceinline__ unsigned fkey(float f) {
    unsigned u = __float_as_uint(f);
    return (u & 0x80000000u) ? ~u : (u | 0x80000000u);
}

// ---------------- seg ensemble kernel ----------------
// seg[c, x, y, z] = tile_last[c, lx,ly,lz] * w[l] / sum_over_covering_tiles(w[lt])
__global__ void seg_kernel(const float* __restrict__ tiles,
                           const float* __restrict__ w,
                           const int*   __restrict__ org,
                           float* __restrict__ out,
                           int T, int C) {
    __shared__ int sorg[128];
    int lt = threadIdx.x;
    if (lt < T * 3 && lt < 128) sorg[lt] = org[lt];
    __syncthreads();

    int v = blockIdx.x * blockDim.x + threadIdx.x;
    if (v >= VVOX) return;
    int z  = v % IMGD;
    int t2 = v / IMGD;
    int y  = t2 % IMGD;
    int x  = t2 / IMGD;

    float wsum = 0.0f, wl = 0.0f;
    int tlast = -1, li = 0;
    #pragma unroll 1
    for (int t = 0; t < T; t++) {
        int lx = x - sorg[t*3 + 0];
        int ly = y - sorg[t*3 + 1];
        int lz = z - sorg[t*3 + 2];
        if ((unsigned)lx < (unsigned)PATCHD &&
            (unsigned)ly < (unsigned)PATCHD &&
            (unsigned)lz < (unsigned)PATCHD) {
            int l = (lx * PATCHD + ly) * PATCHD + lz;
            float wv = __ldg(w + l);
            wsum += wv;
            tlast = t; li = l; wl = wv;
        }
    }
    if (tlast < 0) {
        for (int c = 0; c < C; c++) out[(size_t)c * VVOX + v] = 0.0f / 0.0f;
        return;
    }
    for (int c = 0; c < C; c++) {
        float val = __ldg(tiles + (size_t)(tlast * C + c) * PVOX + li);
        out[(size_t)c * VVOX + v] = val * wl / wsum;
    }
}

// ---------------- top-K selection ----------------
__global__ void hist_kernel(const float* __restrict__ bb, int N) {
    int i = blockIdx.x * blockDim.x + threadIdx.x;
    if (i >= N) return;
    float s = __ldg(bb + (size_t)i * 7 + 6);
    atomicAdd(&g_hist[fkey(s) >> 16], 1u);
}

__global__ void thresh_kernel() {
    __shared__ unsigned csum[1024];
    int tid = threadIdx.x;
    unsigned s = 0;
    int base = tid * 64;
    #pragma unroll 4
    for (int b = 0; b < 64; b++) s += g_hist[base + b];
    csum[tid] = s;
    __syncthreads();
    // inclusive suffix scan (Hillis-Steele)
    for (int off = 1; off < 1024; off <<= 1) {
        unsigned v = (tid + off < 1024) ? csum[tid + off] : 0u;
        __syncthreads();
        csum[tid] += v;
        __syncthreads();
    }
    // this chunk contains the rank-K_PRE boundary?
    if (csum[tid] >= K_PRE && (tid == 1023 || csum[tid + 1] < K_PRE)) {
        unsigned acc = (tid == 1023) ? 0u : csum[tid + 1];
        int bin = base;
        for (int b = 63; b >= 0; b--) {
            acc += g_hist[base + b];
            if (acc >= K_PRE) { bin = base + b; break; }
        }
        g_thresh_bin = bin;
    }
}

__global__ void gather_kernel(const float* __restrict__ bb, int N) {
    int i = blockIdx.x * blockDim.x + threadIdx.x;
    if (i >= N) return;
    float s = __ldg(bb + (size_t)i * 7 + 6);
    unsigned key = fkey(s);
    if ((int)(key >> 16) >= g_thresh_bin) {
        unsigned pos = atomicAdd(&g_cand_count, 1u);
        if (pos < CAND_CAP)
            g_cands[pos] = ((unsigned long long)key << 32) | (unsigned)(~(unsigned)i);
    }
}

// one block, 512 threads: bitonic-sort candidates desc, then prep top-1000 boxes
__global__ void sortprep_kernel(const float* __restrict__ bb,
                                const int* __restrict__ labels) {
    __shared__ unsigned long long sk[CAND_CAP];
    int tid = threadIdx.x;
    unsigned n = g_cand_count;
    if (n > CAND_CAP) n = CAND_CAP;
    for (int i = tid; i < CAND_CAP; i += 512)
        sk[i] = (i < (int)n) ? g_cands[i] : 0ull;
    __syncthreads();

    for (int k = 2; k <= CAND_CAP; k <<= 1) {
        for (int j = k >> 1; j > 0; j >>= 1) {
            for (int i = tid; i < CAND_CAP; i += 512) {
                int l = i ^ j;
                if (l > i) {
                    unsigned long long a = sk[i], b = sk[l];
                    bool descRegion = ((i & k) == 0);
                    bool doSwap = descRegion ? (a < b) : (a > b);
                    if (doSwap) { sk[i] = b; sk[l] = a; }
                }
            }
            __syncthreads();
        }
    }

    for (int r = tid; r < K_PRE; r += 512) {
        unsigned idx = ~((unsigned)sk[r]);
        const float* p = bb + (size_t)idx * 7;
        float sc = __ldg(p + 6);
        int lb = __ldg(labels + idx);
        float off = (float)lb * CLS_OFF;
        bool valid = sc > SCORE_THR;
        #pragma unroll
        for (int d = 0; d < 3; d++) {
            float lo = fminf(fmaxf(__ldg(p + d),     0.0f), (float)IMGD);
            float hi = fminf(fmaxf(__ldg(p + d + 3), 0.0f), (float)IMGD);
            g_box[r*6 + d]     = lo;
            g_box[r*6 + d + 3] = hi;
            g_obox[r*6 + d]     = lo + off;
            g_obox[r*6 + d + 3] = hi + off;
            valid = valid && ((hi - lo) >= MIN_SIZE);
        }
        g_sc[r] = sc;
        g_lab[r] = lb;
        g_validb[r] = valid ? 1 : 0;
    }
}

// ---------------- suppression bitmask ----------------
__global__ void sup_kernel() {
    int i = blockIdx.x;          // 0..K_PRE-1
    int t = threadIdx.x;         // 0..31 -> word index
    float a0 = g_obox[i*6+0], a1 = g_obox[i*6+1], a2 = g_obox[i*6+2];
    float a3 = g_obox[i*6+3], a4 = g_obox[i*6+4], a5 = g_obox[i*6+5];
    float va = ((a3 - a0) * (a4 - a1)) * (a5 - a2);
    unsigned m = 0;
    int base = t * 32;
    #pragma unroll 4
    for (int b = 0; b < 32; b++) {
        int j = base + b;
        if (j < K_PRE && j > i) {
            float b0 = g_obox[j*6+0], b1 = g_obox[j*6+1], b2 = g_obox[j*6+2];
            float b3 = g_obox[j*6+3], b4 = g_obox[j*6+4], b5 = g_obox[j*6+5];
            float cx = fmaxf(fminf(a3, b3) - fmaxf(a0, b0), 0.0f);
            float cy = fmaxf(fminf(a4, b4) - fmaxf(a1, b1), 0.0f);
            float cz = fmaxf(fminf(a5, b5) - fmaxf(a2, b2), 0.0f);
            float inter = (cx * cy) * cz;
            float vb = ((b3 - b0) * (b4 - b1)) * (b5 - b2);
            float uni = fmaxf(va + vb - inter, 1e-6f);
            if (inter / uni > IOU_THR) m |= (1u << b);
        }
    }
    g_sup[i*32 + t] = m;
}

// ---------------- sequential NMS + output (1 warp) ----------------
__global__ void final_kernel(float* __restrict__ dets,   // [100,8]
                             float* __restrict__ labs) { // [100]
    int lane = threadIdx.x;      // 0..31
    unsigned keepw = 0;
    #pragma unroll 4
    for (int b = 0; b < 32; b++) {
        int j = lane * 32 + b;
        if (j < K_PRE && g_validb[j]) keepw |= (1u << b);
    }
    __shared__ int kept[MAX_OUT];
    int nk = 0;
    for (int i = 0; i < K_PRE; i++) {
        unsigned w = __shfl_sync(0xffffffffu, keepw, i >> 5);
        if ((w >> (i & 31)) & 1u) {
            if (lane == 0) kept[nk] = i;
            nk++;
            if (nk == MAX_OUT) break;
            keepw &= ~g_sup[i*32 + lane];
        }
    }
    __syncwarp();
    for (int r = lane; r < MAX_OUT; r += 32) {
        if (r < nk) {
            int i = kept[r];
            #pragma unroll
            for (int d = 0; d < 6; d++) dets[r*8 + d] = g_box[i*6 + d];
            float s = g_sc[i];
            dets[r*8 + 6] = s;
            dets[r*8 + 7] = s;
            labs[r] = (float)g_lab[i];
        } else {
            #pragma unroll
            for (int d = 0; d < 8; d++) dets[r*8 + d] = 0.0f;
            labs[r] = -1.0f;
        }
    }
}

// ---------------- launch ----------------
extern "C" void kernel_launch(void* const* d_in, const int* in_sizes, int n_in,
                              void* d_out, int out_size) {
    const float* tiles  = (const float*)d_in[0];
    const float* w      = (const float*)d_in[1];
    const float* bb     = (const float*)d_in[2];
    const int*   labels = (const int*)  d_in[3];
    const int*   org    = (const int*)  d_in[4];

    int T = in_sizes[4] / 3;
    int C = in_sizes[0] / (T * PVOX);
    int N = in_sizes[2] / 7;
    float* out = (float*)d_out;

    void* hptr = nullptr; cudaGetSymbolAddress(&hptr, g_hist);
    void* cptr = nullptr; cudaGetSymbolAddress(&cptr, g_cand_count);
    cudaMemsetAsync(hptr, 0, NBINS * sizeof(unsigned));
    cudaMemsetAsync(cptr, 0, sizeof(unsigned));

    seg_kernel<<<(VVOX + 255) / 256, 256>>>(tiles, w, org, out, T, C);

    hist_kernel<<<(N + 255) / 256, 256>>>(bb, N);
    thresh_kernel<<<1, 1024>>>();
    gather_kernel<<<(N + 255) / 256, 256>>>(bb, N);
    sortprep_kernel<<<1, 512>>>(bb, labels);
    sup_kernel<<<K_PRE, 32>>>();

    size_t seg_elems = (size_t)C * VVOX;
    final_kernel<<<1, 32>>>(out + seg_elems, out + seg_elems + MAX_OUT * 8);
}

// round 2
// speedup vs baseline: 1.6458x; 1.6458x over previous
#include <cuda_runtime.h>
#include <stdint.h>

#define IMGD   192
#define PATCHD 96
#define PVOX   (PATCHD*PATCHD*PATCHD)         // 884736
#define VVOX   (IMGD*IMGD*IMGD)               // 7077888
#define K_PRE  1000
#define MAX_OUT 100
#define NBINS  65536
#define CAND_CAP 4096
#define SCORE_THR 0.01f
#define MIN_SIZE  0.01f
#define IOU_THR   0.1f
#define CLS_OFF   384.0f   // 2.0 * 192.0

// ---------------- device scratch (no allocations allowed) ----------------
__device__ unsigned int      g_hist[NBINS];
__device__ unsigned int      g_cand_count;
__device__ int               g_thresh_bin;
__device__ unsigned long long g_cands[CAND_CAP];
__device__ float             g_box [K_PRE*6];
__device__ float             g_obox[K_PRE*6];
__device__ float             g_sc  [K_PRE];
__device__ int               g_lab [K_PRE];
__device__ unsigned char     g_validb[K_PRE];
__device__ unsigned int      g_sup [K_PRE*32];

__device__ __forceinline__ unsigned fkey(float f) {
    unsigned u = __float_as_uint(f);
    return (u & 0x80000000u) ? ~u : (u | 0x80000000u);
}

// ---------------- seg ensemble kernel (closed-form coverage, float4) ----------------
// Tile grid is the fixed {0,48,96}^3 meshgrid in 'ij' order: t = ix*9 + iy*3 + iz.
// Per-dim coverage: 1 origin for x<48 or x>=144, else 2 origins {last-48, last}.
// Scan semantics: out gets the LAST covering tile's value * w; cnt accumulates w
// over all covering tiles. seg = tile_last * w / wsum.
__global__ void seg_kernel(const float* __restrict__ tiles,
                           const float* __restrict__ w,
                           float* __restrict__ out,
                           int C) {
    int v4 = blockIdx.x * blockDim.x + threadIdx.x;   // float4-group index
    if (v4 >= VVOX / 4) return;
    int zq = v4 % (IMGD / 4);
    int t2 = v4 / (IMGD / 4);
    int y  = t2 % IMGD;
    int x  = t2 / IMGD;
    int z  = zq * 4;

    // last covering origin index per dim
    int ix = (x >= 96) ? 2 : ((x >= 48) ? 1 : 0);
    int iy = (y >= 96) ? 2 : ((y >= 48) ? 1 : 0);
    int iz = (z >= 96) ? 2 : ((z >= 48) ? 1 : 0);
    int ox = ix * 48, oy = iy * 48, oz = iz * 48;
    bool two_x = (x >= 48) && (x < 144);
    bool two_y = (y >= 48) && (y < 144);
    bool two_z = (z >= 48) && (z < 144);

    int lx = x - ox, ly = y - oy, lz = z - oz;
    int li = (lx * PATCHD + ly) * PATCHD + lz;

    // weight sum over covering tiles (<=8, L2-resident) as float4
    float4 ws = make_float4(0.f, 0.f, 0.f, 0.f);
    float4 wl = make_float4(0.f, 0.f, 0.f, 0.f);
    #pragma unroll
    for (int a = 0; a < 2; a++) {
        if (a == 1 && !two_x) break;
        int xx = lx + a * 48;            // local x in the covering tile
        #pragma unroll
        for (int b = 0; b < 2; b++) {
            if (b == 1 && !two_y) break;
            int yy = ly + b * 48;
            #pragma unroll
            for (int cdim = 0; cdim < 2; cdim++) {
                if (cdim == 1 && !two_z) break;
                int zz = lz + cdim * 48;
                float4 wv = *reinterpret_cast<const float4*>(
                    w + (xx * PATCHD + yy) * PATCHD + zz);
                ws.x += wv.x; ws.y += wv.y; ws.z += wv.z; ws.w += wv.w;
                if (a == 0 && b == 0 && cdim == 0) wl = wv;  // weight at LAST tile's local coords
            }
        }
    }

    int tlast = ix * 9 + iy * 3 + iz;
    int v = v4 * 4;  // linear voxel index == ((x*IMGD)+y)*IMGD + z
    float4 inv = make_float4(wl.x / ws.x, wl.y / ws.y, wl.z / ws.z, wl.w / ws.w);
    for (int c = 0; c < C; c++) {
        float4 tv = *reinterpret_cast<const float4*>(
            tiles + (size_t)(tlast * C + c) * PVOX + li);
        float4 o;
        o.x = tv.x * inv.x; o.y = tv.y * inv.y;
        o.z = tv.z * inv.z; o.w = tv.w * inv.w;
        *reinterpret_cast<float4*>(out + (size_t)c * VVOX + v) = o;
    }
}

// ---------------- top-K selection ----------------
__global__ void hist_kernel(const float* __restrict__ bb, int N) {
    int i = blockIdx.x * blockDim.x + threadIdx.x;
    if (i >= N) return;
    float s = __ldg(bb + (size_t)i * 7 + 6);
    atomicAdd(&g_hist[fkey(s) >> 16], 1u);
}

__global__ void thresh_kernel() {
    __shared__ unsigned csum[1024];
    int tid = threadIdx.x;
    unsigned s = 0;
    int base = tid * 64;
    #pragma unroll 4
    for (int b = 0; b < 64; b++) s += g_hist[base + b];
    csum[tid] = s;
    __syncthreads();
    for (int off = 1; off < 1024; off <<= 1) {
        unsigned v = (tid + off < 1024) ? csum[tid + off] : 0u;
        __syncthreads();
        csum[tid] += v;
        __syncthreads();
    }
    if (csum[tid] >= K_PRE && (tid == 1023 || csum[tid + 1] < K_PRE)) {
        unsigned acc = (tid == 1023) ? 0u : csum[tid + 1];
        int bin = base;
        for (int b = 63; b >= 0; b--) {
            acc += g_hist[base + b];
            if (acc >= K_PRE) { bin = base + b; break; }
        }
        g_thresh_bin = bin;
    }
}

__global__ void gather_kernel(const float* __restrict__ bb, int N) {
    int i = blockIdx.x * blockDim.x + threadIdx.x;
    if (i >= N) return;
    float s = __ldg(bb + (size_t)i * 7 + 6);
    unsigned key = fkey(s);
    if ((int)(key >> 16) >= g_thresh_bin) {
        unsigned pos = atomicAdd(&g_cand_count, 1u);
        if (pos < CAND_CAP)
            g_cands[pos] = ((unsigned long long)key << 32) | (unsigned)(~(unsigned)i);
    }
}

// one block, 1024 threads: bitonic-sort candidates desc, then prep top-1000 boxes
__global__ void sortprep_kernel(const float* __restrict__ bb,
                                const int* __restrict__ labels) {
    __shared__ unsigned long long sk[CAND_CAP];
    int tid = threadIdx.x;
    unsigned n = g_cand_count;
    if (n > CAND_CAP) n = CAND_CAP;
    for (int i = tid; i < CAND_CAP; i += 1024)
        sk[i] = (i < (int)n) ? g_cands[i] : 0ull;
    __syncthreads();

    for (int k = 2; k <= CAND_CAP; k <<= 1) {
        for (int j = k >> 1; j > 0; j >>= 1) {
            for (int i = tid; i < CAND_CAP; i += 1024) {
                int l = i ^ j;
                if (l > i) {
                    unsigned long long a = sk[i], b = sk[l];
                    bool descRegion = ((i & k) == 0);
                    bool doSwap = descRegion ? (a < b) : (a > b);
                    if (doSwap) { sk[i] = b; sk[l] = a; }
                }
            }
            __syncthreads();
        }
    }

    for (int r = tid; r < K_PRE; r += 1024) {
        unsigned idx = ~((unsigned)sk[r]);
        const float* p = bb + (size_t)idx * 7;
        float sc = __ldg(p + 6);
        int lb = __ldg(labels + idx);
        float off = (float)lb * CLS_OFF;
        bool valid = sc > SCORE_THR;
        #pragma unroll
        for (int d = 0; d < 3; d++) {
            float lo = fminf(fmaxf(__ldg(p + d),     0.0f), (float)IMGD);
            float hi = fminf(fmaxf(__ldg(p + d + 3), 0.0f), (float)IMGD);
            g_box[r*6 + d]     = lo;
            g_box[r*6 + d + 3] = hi;
            g_obox[r*6 + d]     = lo + off;
            g_obox[r*6 + d + 3] = hi + off;
            valid = valid && ((hi - lo) >= MIN_SIZE);
        }
        g_sc[r] = sc;
        g_lab[r] = lb;
        g_validb[r] = valid ? 1 : 0;
    }
}

// ---------------- suppression bitmask ----------------
__global__ void sup_kernel() {
    int i = blockIdx.x;          // 0..K_PRE-1
    int t = threadIdx.x;         // 0..31 -> word index
    float a0 = g_obox[i*6+0], a1 = g_obox[i*6+1], a2 = g_obox[i*6+2];
    float a3 = g_obox[i*6+3], a4 = g_obox[i*6+4], a5 = g_obox[i*6+5];
    float va = ((a3 - a0) * (a4 - a1)) * (a5 - a2);
    unsigned m = 0;
    int base = t * 32;
    #pragma unroll 4
    for (int b = 0; b < 32; b++) {
        int j = base + b;
        if (j < K_PRE && j > i) {
            float b0 = g_obox[j*6+0], b1 = g_obox[j*6+1], b2 = g_obox[j*6+2];
            float b3 = g_obox[j*6+3], b4 = g_obox[j*6+4], b5 = g_obox[j*6+5];
            float cx = fmaxf(fminf(a3, b3) - fmaxf(a0, b0), 0.0f);
            float cy = fmaxf(fminf(a4, b4) - fmaxf(a1, b1), 0.0f);
            float cz = fmaxf(fminf(a5, b5) - fmaxf(a2, b2), 0.0f);
            float inter = (cx * cy) * cz;
            float vb = ((b3 - b0) * (b4 - b1)) * (b5 - b2);
            float uni = fmaxf(va + vb - inter, 1e-6f);
            if (inter / uni > IOU_THR) m |= (1u << b);
        }
    }
    g_sup[i*32 + t] = m;
}

// ---------------- sequential NMS + output (1 warp) ----------------
__global__ void final_kernel(float* __restrict__ dets,   // [100,8]
                             float* __restrict__ labs) { // [100]
    int lane = threadIdx.x;      // 0..31
    unsigned keepw = 0;
    #pragma unroll 4
    for (int b = 0; b < 32; b++) {
        int j = lane * 32 + b;
        if (j < K_PRE && g_validb[j]) keepw |= (1u << b);
    }
    __shared__ int kept[MAX_OUT];
    int nk = 0;
    for (int i = 0; i < K_PRE; i++) {
        unsigned w = __shfl_sync(0xffffffffu, keepw, i >> 5);
        if ((w >> (i & 31)) & 1u) {
            if (lane == 0) kept[nk] = i;
            nk++;
            if (nk == MAX_OUT) break;
            keepw &= ~g_sup[i*32 + lane];
        }
    }
    __syncwarp();
    for (int r = lane; r < MAX_OUT; r += 32) {
        if (r < nk) {
            int i = kept[r];
            #pragma unroll
            for (int d = 0; d < 6; d++) dets[r*8 + d] = g_box[i*6 + d];
            float s = g_sc[i];
            dets[r*8 + 6] = s;
            dets[r*8 + 7] = s;
            labs[r] = (float)g_lab[i];
        } else {
            #pragma unroll
            for (int d = 0; d < 8; d++) dets[r*8 + d] = 0.0f;
            labs[r] = -1.0f;
        }
    }
}

// ---------------- launch ----------------
extern "C" void kernel_launch(void* const* d_in, const int* in_sizes, int n_in,
                              void* d_out, int out_size) {
    const float* tiles  = (const float*)d_in[0];
    const float* w      = (const float*)d_in[1];
    const float* bb     = (const float*)d_in[2];
    const int*   labels = (const int*)  d_in[3];

    int T = in_sizes[4] / 3;
    int C = in_sizes[0] / (T * PVOX);
    int N = in_sizes[2] / 7;
    float* out = (float*)d_out;

    void* hptr = nullptr; cudaGetSymbolAddress(&hptr, g_hist);
    void* cptr = nullptr; cudaGetSymbolAddress(&cptr, g_cand_count);
    cudaMemsetAsync(hptr, 0, NBINS * sizeof(unsigned));
    cudaMemsetAsync(cptr, 0, sizeof(unsigned));

    seg_kernel<<<(VVOX / 4 + 255) / 256, 256>>>(tiles, w, out, C);

    hist_kernel<<<(N + 255) / 256, 256>>>(bb, N);
    thresh_kernel<<<1, 1024>>>();
    gather_kernel<<<(N + 255) / 256, 256>>>(bb, N);
    sortprep_kernel<<<1, 1024>>>(bb, labels);
    sup_kernel<<<K_PRE, 32>>>();

    size_t seg_elems = (size_t)C * VVOX;
    final_kernel<<<1, 32>>>(out + seg_elems, out + seg_elems + MAX_OUT * 8);
}